// round 8
// baseline (speedup 1.0000x reference)
#include <cuda_runtime.h>
#include <math.h>

#define HW    256
#define NBAT  8          // batches per warp (= per block)
#define EPL   11         // support entries per lane (4 lanes/batch -> 44 >= 42 needed)
#define FULLM 0xffffffffu
#define EPSF  1e-9f
#define MINNORM 1.17549435e-38f

// --- fp32 ops with flush-to-zero, matching XLA:GPU ftz semantics ---
__device__ __forceinline__ float fmul_ftz(float a, float b) {
    float r; asm("mul.rn.ftz.f32 %0,%1,%2;" : "=f"(r) : "f"(a), "f"(b)); return r;
}
__device__ __forceinline__ float ffma_ftz(float a, float b, float c) {
    float r; asm("fma.rn.ftz.f32 %0,%1,%2,%3;" : "=f"(r) : "f"(a), "f"(b), "f"(c)); return r;
}
__device__ __forceinline__ float fadd_ftz(float a, float b) {
    float r; asm("add.rn.ftz.f32 %0,%1,%2;" : "=f"(r) : "f"(a), "f"(b)); return r;
}

__global__ __launch_bounds__(32, 1) void spair_obj_kl_kernel(
    const float* __restrict__ z_pres,
    const float* __restrict__ z_prob,
    float* __restrict__ out)
{
    // padded rows: s_step stride 257 float4 (1028 words % 32 = 4) -> conflict-free
    // group broadcasts; s_kl stride 260 (4 mod 32) -> conflict-free scatter writes
    __shared__ float4 s_step[NBAT][HW + 1];   // {sample, csf, prob, c0} per (batch, step)
    __shared__ float  s_kl[NBAT][HW + 4];
    __shared__ float  s_invd[HW];

    const int lane  = threadIdx.x;
    const int bbase = blockIdx.x * NBAT;
    const int sub   = lane & 3;     // lane within batch group
    const int g     = lane >> 2;    // batch group 0..7

    for (int i = lane; i < HW; i += 32) s_invd[i] = 1.0f / (float)(HW - i);

    // ---- preamble: stage each batch (whole warp cooperates per batch) ----
    #pragma unroll 1
    for (int bb = 0; bb < NBAT; bb++) {
        const float4* zp4 = (const float4*)(z_pres + (size_t)(bbase + bb) * HW);
        const float4* pb4 = (const float4*)(z_prob + (size_t)(bbase + bb) * HW);
        float4 a0 = zp4[lane*2], a1 = zp4[lane*2+1];
        float4 p0 = pb4[lane*2], p1 = pb4[lane*2+1];

        float smp[8] = { rintf(a0.x), rintf(a0.y), rintf(a0.z), rintf(a0.w),
                         rintf(a1.x), rintf(a1.y), rintf(a1.z), rintf(a1.w) };
        float prv[8] = { p0.x, p0.y, p0.z, p0.w, p1.x, p1.y, p1.z, p1.w };

        float tot = 0.f;
        #pragma unroll
        for (int k = 0; k < 8; k++) tot += smp[k];
        float incl = tot;
        #pragma unroll
        for (int off = 1; off < 32; off <<= 1) {
            float o = __shfl_up_sync(FULLM, incl, off);
            if (lane >= off) incl += o;
        }
        float run = incl - tot;   // exclusive prefix (csf BEFORE step lane*8)
        #pragma unroll
        for (int k = 0; k < 8; k++) {
            int i = lane*8 + k;
            float pr = prv[k];
            float c0 = pr * __logf(pr + EPSF)
                     + (1.0f - pr) * __logf(1.0f - pr + EPSF);
            s_step[bb][i] = make_float4(smp[k], run, pr, c0);
            run += smp[k];
        }
    }
    __syncwarp();

    // ---- initial count distribution cd0[j] ~ (1-p) p^j, normalized, FTZ ----
    // (bit-identical to full-support version: entries j>=42 flush to exact 0)
    float e2   = (float)exp(2.0);
    float pf   = 1.0f / (e2 + 1.0f);
    float onem = 1.0f - pf;
    double pw[9];
    pw[0] = (double)pf;
    #pragma unroll
    for (int k = 1; k < 9; k++) pw[k] = pw[k-1] * pw[k-1];

    float cd[EPL], fj[EPL];
    #pragma unroll
    for (int k = 0; k < EPL; k++) {
        int j = sub * EPL + k;                  // 0..43
        double acc = 1.0;
        int jj = j;
        #pragma unroll
        for (int q = 0; q < 9; q++) { if (jj & 1) acc *= pw[q]; jj >>= 1; }
        float wv = (float)acc * onem;
        if (wv < MINNORM) wv = 0.0f;            // ftz flush
        cd[k] = wv;
        fj[k] = (float)j;
    }
    // wsum = sum over support (only nonzero entries contribute; == full-sum value set)
    float w0 = ((cd[0]+cd[1]) + (cd[2]+cd[3])) + ((cd[4]+cd[5]) + (cd[6]+cd[7]));
    float wsum = w0 + ((cd[8]+cd[9]) + cd[10]);
    wsum += __shfl_xor_sync(FULLM, wsum, 1);
    wsum += __shfl_xor_sync(FULLM, wsum, 2);
    #pragma unroll
    for (int k = 0; k < EPL; k++) {
        float v = cd[k] / wsum;
        if (v < MINNORM) v = 0.0f;
        cd[k] = v;
    }

    const float LEPS = __logf(EPSF);
    int die = HW;

    float4 st = s_step[g][0];
    // ---- serial scan: 8 batches in parallel (4 lanes each), ftz fp32 ----
    #pragma unroll 1
    for (int i = 0; i < HW; i++) {
        float4 nst = s_step[g][i + 1];          // prefetch ([HW] slot is padding)
        float sA = st.x, cs = st.y, pr = st.z, c0 = st.w;
        float ivd = s_invd[i];
        float d   = (float)(HW - i);
        float s1  = 1.0f - sA;                  // mult = s2*pzg + s1
        float s2  = sA + sA - 1.0f;

        float num0 = 0.f, num1 = 0.f;
        #pragma unroll
        for (int k = 0; k < EPL; k++) {
            float t = fminf(fmaxf(fj[k] - cs, 0.0f), d);
            float pzg = fmul_ftz(t, ivd);                 // clip(j-csf,0,d)/d
            if (k & 1) num1 = ffma_ftz(cd[k], pzg, num1); // p_z uses OLD cd
            else       num0 = ffma_ftz(cd[k], pzg, num0);
            float m = ffma_ftz(s2, pzg, s1);
            cd[k] = fmul_ftz(m, cd[k]);                   // ftz tail flush like ref
        }
        // nrm: depth-4 register tree over updated cd
        float p0 = fadd_ftz(cd[0], cd[1]);
        float p1 = fadd_ftz(cd[2], cd[3]);
        float p2 = fadd_ftz(cd[4], cd[5]);
        float p3 = fadd_ftz(cd[6], cd[7]);
        float p4 = fadd_ftz(cd[8], cd[9]);
        float q0 = fadd_ftz(p0, p1);
        float q1 = fadd_ftz(p2, p3);
        float q2 = fadd_ftz(p4, cd[10]);
        float nrm = fadd_ftz(fadd_ftz(q0, q1), q2);
        float num = fadd_ftz(num0, num1);
        // 2-level butterfly within 4-lane group
        num = fadd_ftz(num, __shfl_xor_sync(FULLM, num, 1));
        num = fadd_ftz(num, __shfl_xor_sync(FULLM, num, 2));
        nrm = fadd_ftz(nrm, __shfl_xor_sync(FULLM, nrm, 1));
        nrm = fadd_ftz(nrm, __shfl_xor_sync(FULLM, nrm, 2));

        if (sub == 0) {
            float lpz  = __logf(num + EPSF);
            float l1pz = __logf(1.0f - num + EPSF);
            s_kl[g][i] = c0 - pr * lpz - (1.0f - pr) * l1pz;
        }

        // all 8 batches dead (cd identically 0 forever) -> closed-form tail
        if (__all_sync(FULLM, nrm == 0.0f)) { die = i + 1; break; }

        float invn = 1.0f / fmaxf(nrm, 1e-6f);
        #pragma unroll
        for (int k = 0; k < EPL; k++) cd[k] = fmul_ftz(cd[k], invn);
        st = nst;
    }

    // ---- dead tail: p_z == 0 -> kl = c0 - prob*log(eps) ----
    for (int i = die + sub; i < HW; i += 4) {
        float4 stv = s_step[g][i];
        s_kl[g][i] = stv.w - stv.z * LEPS;
    }
    __syncwarp();

    // ---- coalesced float4 store (un-pad rows in registers) ----
    float* ob = out + (size_t)bbase * HW;
    #pragma unroll
    for (int q = 0; q < 16; q++) {
        int idx = q * 32 + lane;        // float4 index within 2048 output floats
        int fo  = idx * 4;
        int bb  = fo >> 8;
        int off = fo & 255;
        float4 v = make_float4(s_kl[bb][off], s_kl[bb][off+1],
                               s_kl[bb][off+2], s_kl[bb][off+3]);
        ((float4*)ob)[idx] = v;
    }
}

extern "C" void kernel_launch(void* const* d_in, const int* in_sizes, int n_in,
                              void* d_out, int out_size)
{
    const float* z_pres = (const float*)d_in[0];
    const float* z_prob = (const float*)d_in[1];
    float* out = (float*)d_out;
    int B = in_sizes[0] / HW;            // 1024
    spair_obj_kl_kernel<<<B / NBAT, 32>>>(z_pres, z_prob, out);
}

// round 9
// speedup vs baseline: 1.9126x; 1.9126x over previous
#include <cuda_runtime.h>
#include <math.h>

#define HW    256
#define NWARP 8
#define EPL   6          // support entries per lane; 8-lane group covers j=0..47 (>=42 needed)
#define FULLM 0xffffffffu
#define EPSF  1e-9f
#define MINNORM 1.17549435e-38f

// --- fp32 ops with flush-to-zero, matching XLA:GPU ftz semantics ---
__device__ __forceinline__ float fmul_ftz(float a, float b) {
    float r; asm("mul.rn.ftz.f32 %0,%1,%2;" : "=f"(r) : "f"(a), "f"(b)); return r;
}
__device__ __forceinline__ float ffma_ftz(float a, float b, float c) {
    float r; asm("fma.rn.ftz.f32 %0,%1,%2,%3;" : "=f"(r) : "f"(a), "f"(b), "f"(c)); return r;
}
__device__ __forceinline__ float fadd_ftz(float a, float b) {
    float r; asm("add.rn.ftz.f32 %0,%1,%2;" : "=f"(r) : "f"(a), "f"(b)); return r;
}

__global__ __launch_bounds__(NWARP*32, 1) void spair_obj_kl_kernel(
    const float* __restrict__ z_pres,
    const float* __restrict__ z_prob,
    float* __restrict__ out)
{
    __shared__ float4 s_step[NWARP][HW + 1];   // {sample, csf, prob, c0} per (warp-batch, step)
    __shared__ float  s_kl[NWARP][HW + 4];
    __shared__ float  s_invd[NWARP][HW/32 == 8 ? HW : HW];  // per-warp copy -> no cross-warp sync

    const int tid  = threadIdx.x;
    const int lane = tid & 31;
    const int w    = tid >> 5;
    const int b    = blockIdx.x * NWARP + w;
    const int sub  = lane & 7;      // lane within 8-lane replica group

    // per-warp private invd table (redundant across warps; avoids __syncthreads)
    #pragma unroll
    for (int i = lane; i < HW; i += 32) s_invd[w][i] = 1.0f / (float)(HW - i);

    // ---- preamble: stage this warp's batch (32 lanes cooperate) ----
    {
        const float4* zp4 = (const float4*)(z_pres + (size_t)b * HW);
        const float4* pb4 = (const float4*)(z_prob + (size_t)b * HW);
        float4 a0 = zp4[lane*2], a1 = zp4[lane*2+1];
        float4 p0 = pb4[lane*2], p1 = pb4[lane*2+1];

        float smp[8] = { rintf(a0.x), rintf(a0.y), rintf(a0.z), rintf(a0.w),
                         rintf(a1.x), rintf(a1.y), rintf(a1.z), rintf(a1.w) };
        float prv[8] = { p0.x, p0.y, p0.z, p0.w, p1.x, p1.y, p1.z, p1.w };

        float tot = 0.f;
        #pragma unroll
        for (int k = 0; k < 8; k++) tot += smp[k];
        float incl = tot;
        #pragma unroll
        for (int off = 1; off < 32; off <<= 1) {
            float o = __shfl_up_sync(FULLM, incl, off);
            if (lane >= off) incl += o;
        }
        float run = incl - tot;   // exclusive prefix (csf BEFORE step lane*8)
        #pragma unroll
        for (int k = 0; k < 8; k++) {
            int i = lane*8 + k;
            float pr = prv[k];
            float c0 = pr * __logf(pr + EPSF)
                     + (1.0f - pr) * __logf(1.0f - pr + EPSF);
            s_step[w][i] = make_float4(smp[k], run, pr, c0);
            run += smp[k];
        }
    }
    __syncwarp();

    // ---- initial count distribution cd0[j] ~ (1-p) p^j, normalized, FTZ ----
    // 8-lane group holds j = sub + 8k, k=0..5 (0..47); entries >=42 flush to exact 0.
    // All four groups are identical replicas.
    float e2   = (float)exp(2.0);
    float pf   = 1.0f / (e2 + 1.0f);
    float onem = 1.0f - pf;
    double pw[9];
    pw[0] = (double)pf;
    #pragma unroll
    for (int k = 1; k < 9; k++) pw[k] = pw[k-1] * pw[k-1];

    float cd[EPL], fj[EPL];
    #pragma unroll
    for (int k = 0; k < EPL; k++) {
        int j = sub + 8*k;                      // 0..47
        double acc = 1.0;
        int jj = j;
        #pragma unroll
        for (int q = 0; q < 9; q++) { if (jj & 1) acc *= pw[q]; jj >>= 1; }
        float wv = (float)acc * onem;
        if (wv < MINNORM) wv = 0.0f;            // ftz flush
        cd[k] = wv;
        fj[k] = (float)j;
    }
    float wsum = ((cd[0]+cd[1]) + (cd[2]+cd[3])) + (cd[4]+cd[5]);
    wsum += __shfl_xor_sync(FULLM, wsum, 1);
    wsum += __shfl_xor_sync(FULLM, wsum, 2);
    wsum += __shfl_xor_sync(FULLM, wsum, 4);
    #pragma unroll
    for (int k = 0; k < EPL; k++) {
        float v = cd[k] / wsum;
        if (v < MINNORM) v = 0.0f;
        cd[k] = v;
    }

    const float LEPS = __logf(EPSF);
    int pin = HW;                // first step from which kl == dead closed-form

    float4 st = s_step[w][0];
    // ---- serial scan, ftz fp32; 4 replica groups, 3-level butterfly ----
    #pragma unroll 1
    for (int i = 0; i < HW; i++) {
        float4 nst = s_step[w][i + 1];          // prefetch ([HW] slot is padding)
        float sA = st.x, cs = st.y, pr = st.z, c0 = st.w;
        float ivd = s_invd[w][i];
        float d   = (float)(HW - i);
        float s1  = 1.0f - sA;                  // mult = s2*pzg + s1
        float s2  = sA + sA - 1.0f;

        float num0 = 0.f, num1 = 0.f;
        float alive = 0.f;                      // >0 iff some surviving entry has j > csf
        #pragma unroll
        for (int k = 0; k < EPL; k++) {
            float t = fminf(fmaxf(fj[k] - cs, 0.0f), d);
            float pzg = fmul_ftz(t, ivd);                 // clip(j-csf,0,d)/d
            if (k & 1) num1 = ffma_ftz(cd[k], pzg, num1); // p_z uses OLD cd
            else       num0 = ffma_ftz(cd[k], pzg, num0);
            float m = ffma_ftz(s2, pzg, s1);
            cd[k] = fmul_ftz(m, cd[k]);                   // ftz tail flush like ref
            alive = fmaxf(alive, fminf(cd[k], t));        // both >0 <=> entry above csf survives
        }
        float p0 = fadd_ftz(cd[0], cd[1]);
        float p1 = fadd_ftz(cd[2], cd[3]);
        float p2 = fadd_ftz(cd[4], cd[5]);
        float nrm = fadd_ftz(fadd_ftz(p0, p1), p2);
        float num = fadd_ftz(num0, num1);
        // 3-level butterfly within each 8-lane replica group
        num = fadd_ftz(num, __shfl_xor_sync(FULLM, num, 1));
        nrm = fadd_ftz(nrm, __shfl_xor_sync(FULLM, nrm, 1));
        num = fadd_ftz(num, __shfl_xor_sync(FULLM, num, 2));
        nrm = fadd_ftz(nrm, __shfl_xor_sync(FULLM, nrm, 2));
        num = fadd_ftz(num, __shfl_xor_sync(FULLM, num, 4));
        nrm = fadd_ftz(nrm, __shfl_xor_sync(FULLM, nrm, 4));

        if (lane == 0) {
            float lpz  = __logf(num + EPSF);
            float l1pz = __logf(1.0f - num + EPSF);
            s_kl[w][i] = c0 - pr * lpz - (1.0f - pr) * l1pz;
        }

        // pinned: no surviving support above csf -> num==0 exactly forever,
        // kl == dead closed-form for all remaining steps (absorbing state).
        if (!__any_sync(FULLM, alive > 0.0f)) { pin = i + 1; break; }

        float invn = 1.0f / fmaxf(nrm, 1e-6f);
        #pragma unroll
        for (int k = 0; k < EPL; k++) cd[k] = fmul_ftz(cd[k], invn);
        st = nst;
    }

    // ---- pinned tail: p_z == 0 exactly -> kl = c0 - prob*log(eps) ----
    for (int i = pin + lane; i < HW; i += 32) {
        float4 stv = s_step[w][i];
        s_kl[w][i] = stv.w - stv.z * LEPS;
    }
    __syncwarp();

    // ---- coalesced float4 store of this warp's row ----
    float* ob = out + (size_t)b * HW;
    #pragma unroll
    for (int q = 0; q < 2; q++) {
        int base = lane*8 + q*4;
        float4 v = make_float4(s_kl[w][base], s_kl[w][base+1],
                               s_kl[w][base+2], s_kl[w][base+3]);
        ((float4*)ob)[lane*2 + q] = v;
    }
}

extern "C" void kernel_launch(void* const* d_in, const int* in_sizes, int n_in,
                              void* d_out, int out_size)
{
    const float* z_pres = (const float*)d_in[0];
    const float* z_prob = (const float*)d_in[1];
    float* out = (float*)d_out;
    int B = in_sizes[0] / HW;            // 1024
    spair_obj_kl_kernel<<<B / NWARP, NWARP*32>>>(z_pres, z_prob, out);
}

// round 12
// speedup vs baseline: 2.0479x; 1.0707x over previous
#include <cuda_runtime.h>
#include <math.h>

#define HW    256
#define NWARP 8
#define EPL   6          // support entries per lane; 8-lane group covers j=0..47 (>=42 needed)
#define FULLM 0xffffffffu
#define EPSF  1e-9f
#define MINNORM 1.17549435e-38f

// --- fp32 ops with flush-to-zero, matching XLA:GPU ftz semantics ---
__device__ __forceinline__ float fmul_ftz(float a, float b) {
    float r; asm("mul.rn.ftz.f32 %0,%1,%2;" : "=f"(r) : "f"(a), "f"(b)); return r;
}
__device__ __forceinline__ float ffma_ftz(float a, float b, float c) {
    float r; asm("fma.rn.ftz.f32 %0,%1,%2,%3;" : "=f"(r) : "f"(a), "f"(b), "f"(c)); return r;
}
__device__ __forceinline__ float fadd_ftz(float a, float b) {
    float r; asm("add.rn.ftz.f32 %0,%1,%2;" : "=f"(r) : "f"(a), "f"(b)); return r;
}
__device__ __forceinline__ float frcp_approx(float a) {
    float r; asm("rcp.approx.ftz.f32 %0,%1;" : "=f"(r) : "f"(a)); return r;
}

__global__ __launch_bounds__(NWARP*32, 1) void spair_obj_kl_kernel(
    const float* __restrict__ z_pres,
    const float* __restrict__ z_prob,
    float* __restrict__ out)
{
    __shared__ float4 s_step[NWARP][HW + 1];   // {sample, csf, prob, c0} per (warp-batch, step)
    __shared__ float  s_kl[NWARP][HW + 4];
    __shared__ float  s_invd[NWARP][HW];       // per-warp copy -> no cross-warp sync

    const int tid  = threadIdx.x;
    const int lane = tid & 31;
    const int w    = tid >> 5;
    const int b    = blockIdx.x * NWARP + w;
    const int sub  = lane & 7;      // lane within 8-lane replica group

    #pragma unroll
    for (int i = lane; i < HW; i += 32) s_invd[w][i] = 1.0f / (float)(HW - i);

    // ---- preamble: stage this warp's batch (32 lanes cooperate) ----
    {
        const float4* zp4 = (const float4*)(z_pres + (size_t)b * HW);
        const float4* pb4 = (const float4*)(z_prob + (size_t)b * HW);
        float4 a0 = zp4[lane*2], a1 = zp4[lane*2+1];
        float4 p0 = pb4[lane*2], p1 = pb4[lane*2+1];

        float smp[8] = { rintf(a0.x), rintf(a0.y), rintf(a0.z), rintf(a0.w),
                         rintf(a1.x), rintf(a1.y), rintf(a1.z), rintf(a1.w) };
        float prv[8] = { p0.x, p0.y, p0.z, p0.w, p1.x, p1.y, p1.z, p1.w };

        float tot = 0.f;
        #pragma unroll
        for (int k = 0; k < 8; k++) tot += smp[k];
        float incl = tot;
        #pragma unroll
        for (int off = 1; off < 32; off <<= 1) {
            float o = __shfl_up_sync(FULLM, incl, off);
            if (lane >= off) incl += o;
        }
        float run = incl - tot;   // exclusive prefix (csf BEFORE step lane*8)
        #pragma unroll
        for (int k = 0; k < 8; k++) {
            int i = lane*8 + k;
            float pr = prv[k];
            float c0 = pr * __logf(pr + EPSF)
                     + (1.0f - pr) * __logf(1.0f - pr + EPSF);
            s_step[w][i] = make_float4(smp[k], run, pr, c0);
            run += smp[k];
        }
    }
    __syncwarp();

    // ---- initial count distribution cd0[j] ~ (1-p) p^j, normalized, FTZ ----
    // 8-lane group holds j = sub + 8k, k=0..5 (0..47); entries >=42 flush to exact 0.
    float e2   = (float)exp(2.0);
    float pf   = 1.0f / (e2 + 1.0f);
    float onem = 1.0f - pf;
    double pw[9];
    pw[0] = (double)pf;
    #pragma unroll
    for (int k = 1; k < 9; k++) pw[k] = pw[k-1] * pw[k-1];

    float cd[EPL], fj[EPL];
    #pragma unroll
    for (int k = 0; k < EPL; k++) {
        int j = sub + 8*k;                      // 0..47
        double acc = 1.0;
        int jj = j;
        #pragma unroll
        for (int q = 0; q < 9; q++) { if (jj & 1) acc *= pw[q]; jj >>= 1; }
        float wv = (float)acc * onem;
        if (wv < MINNORM) wv = 0.0f;            // ftz flush
        cd[k] = wv;
        fj[k] = (float)j;
    }
    float wsum = ((cd[0]+cd[1]) + (cd[2]+cd[3])) + (cd[4]+cd[5]);
    wsum += __shfl_xor_sync(FULLM, wsum, 1);
    wsum += __shfl_xor_sync(FULLM, wsum, 2);
    wsum += __shfl_xor_sync(FULLM, wsum, 4);
    #pragma unroll
    for (int k = 0; k < EPL; k++) {
        float v = cd[k] / wsum;
        if (v < MINNORM) v = 0.0f;
        cd[k] = v;
    }

    const float LEPS = __logf(EPSF);
    int pin = HW;                // first step from which kl == dead closed-form
    int exitf = 0;               // deferred pinned flag (vote from PREVIOUS step)

    float4 st = s_step[w][0];
    // ---- serial scan, ftz fp32; 4 replica groups, 3-level butterfly ----
    #pragma unroll 1
    for (int i = 0; i < HW; i++) {
        // deferred exit: predicate resolved a full iteration ago -> no issue stall
        if (exitf) { pin = i; break; }

        float4 nst = s_step[w][i + 1];          // prefetch ([HW] slot is padding)
        float sA = st.x, cs = st.y, pr = st.z, c0 = st.w;
        float ivd = s_invd[w][i];
        float d   = (float)(HW - i);
        float s1  = 1.0f - sA;                  // mult = s2*pzg + s1
        float s2  = sA + sA - 1.0f;

        float num0 = 0.f, num1 = 0.f;
        float alive = 0.f;                      // >0 iff some surviving entry has j > csf
        #pragma unroll
        for (int k = 0; k < EPL; k++) {
            float t = fminf(fmaxf(fj[k] - cs, 0.0f), d);
            float pzg = fmul_ftz(t, ivd);                 // clip(j-csf,0,d)/d
            if (k & 1) num1 = ffma_ftz(cd[k], pzg, num1); // p_z uses OLD cd
            else       num0 = ffma_ftz(cd[k], pzg, num0);
            float m = ffma_ftz(s2, pzg, s1);
            cd[k] = fmul_ftz(m, cd[k]);                   // ftz tail flush like ref
            alive = fmaxf(alive, fminf(cd[k], t));        // both >0 <=> entry above csf survives
        }
        // vote issues here; its result is only consumed at NEXT iteration's top,
        // so VOTE latency hides under the butterfly + log work below.
        exitf = !__any_sync(FULLM, alive > 0.0f);

        float p0 = fadd_ftz(cd[0], cd[1]);
        float p1 = fadd_ftz(cd[2], cd[3]);
        float p2 = fadd_ftz(cd[4], cd[5]);
        float nrm = fadd_ftz(fadd_ftz(p0, p1), p2);
        float num = fadd_ftz(num0, num1);
        // 3-level butterfly within each 8-lane replica group
        num = fadd_ftz(num, __shfl_xor_sync(FULLM, num, 1));
        nrm = fadd_ftz(nrm, __shfl_xor_sync(FULLM, nrm, 1));
        num = fadd_ftz(num, __shfl_xor_sync(FULLM, num, 2));
        nrm = fadd_ftz(nrm, __shfl_xor_sync(FULLM, nrm, 2));
        num = fadd_ftz(num, __shfl_xor_sync(FULLM, num, 4));
        nrm = fadd_ftz(nrm, __shfl_xor_sync(FULLM, nrm, 4));

        if (lane == 0) {
            float lpz  = __logf(num + EPSF);
            float l1pz = __logf(1.0f - num + EPSF);
            s_kl[w][i] = c0 - pr * lpz - (1.0f - pr) * l1pz;
        }

        // renorm: approx reciprocal (clip semantics preserved); scale-only
        // 1-ulp perturbation is removed by the next normalization.
        float invn = frcp_approx(fmaxf(nrm, 1e-6f));
        #pragma unroll
        for (int k = 0; k < EPL; k++) cd[k] = fmul_ftz(cd[k], invn);
        st = nst;
    }

    // ---- pinned tail: p_z == 0 exactly -> kl = c0 - prob*log(eps) ----
    for (int i = pin + lane; i < HW; i += 32) {
        float4 stv = s_step[w][i];
        s_kl[w][i] = stv.w - stv.z * LEPS;
    }
    __syncwarp();

    // ---- coalesced float4 store of this warp's row ----
    float* ob = out + (size_t)b * HW;
    #pragma unroll
    for (int q = 0; q < 2; q++) {
        int base = lane*8 + q*4;
        float4 v = make_float4(s_kl[w][base], s_kl[w][base+1],
                               s_kl[w][base+2], s_kl[w][base+3]);
        ((float4*)ob)[lane*2 + q] = v;
    }
}

extern "C" void kernel_launch(void* const* d_in, const int* in_sizes, int n_in,
                              void* d_out, int out_size)
{
    const float* z_pres = (const float*)d_in[0];
    const float* z_prob = (const float*)d_in[1];
    float* out = (float*)d_out;
    int B = in_sizes[0] / HW;            // 1024
    spair_obj_kl_kernel<<<B / NWARP, NWARP*32>>>(z_pres, z_prob, out);
}

// round 15
// speedup vs baseline: 2.6139x; 1.2764x over previous
#include <cuda_runtime.h>
#include <math.h>

#define HW    256
#define NWARP 8
#define EPL   6          // support entries per lane; 8-lane group covers j=0..47 (>=42 needed)
#define FULLM 0xffffffffu
#define EPSF  1e-9f
#define MINNORM 1.17549435e-38f

// --- fp32 ops with flush-to-zero, matching XLA:GPU ftz semantics ---
__device__ __forceinline__ float fmul_ftz(float a, float b) {
    float r; asm("mul.rn.ftz.f32 %0,%1,%2;" : "=f"(r) : "f"(a), "f"(b)); return r;
}
__device__ __forceinline__ float ffma_ftz(float a, float b, float c) {
    float r; asm("fma.rn.ftz.f32 %0,%1,%2,%3;" : "=f"(r) : "f"(a), "f"(b), "f"(c)); return r;
}
__device__ __forceinline__ float fadd_ftz(float a, float b) {
    float r; asm("add.rn.ftz.f32 %0,%1,%2;" : "=f"(r) : "f"(a), "f"(b)); return r;
}
__device__ __forceinline__ float frcp_approx(float a) {
    float r; asm("rcp.approx.ftz.f32 %0,%1;" : "=f"(r) : "f"(a)); return r;
}

__global__ __launch_bounds__(NWARP*32, 1) void spair_obj_kl_kernel(
    const float* __restrict__ z_pres,
    const float* __restrict__ z_prob,
    float* __restrict__ out)
{
    __shared__ float2 s_sc[NWARP][HW];     // {sample, csf} — loop state
    __shared__ float2 s_pc[NWARP][HW];     // {prob, c0}   — epilogue only
    __shared__ float  s_num[NWARP][HW];    // reduced p_z per step (0 if never reached)
    __shared__ float  s_invd[NWARP][HW];   // per-warp copy -> no cross-warp sync

    const int tid  = threadIdx.x;
    const int lane = tid & 31;
    const int w    = tid >> 5;
    const int b    = blockIdx.x * NWARP + w;
    const int sub  = lane & 7;      // lane within 8-lane replica group

    #pragma unroll
    for (int i = lane; i < HW; i += 32) {
        s_invd[w][i] = 1.0f / (float)(HW - i);
        s_num[w][i]  = 0.0f;        // pinned/unreached steps -> num=0 -> exact closed form
    }

    // ---- preamble: stage this warp's batch (32 lanes cooperate) ----
    {
        const float4* zp4 = (const float4*)(z_pres + (size_t)b * HW);
        const float4* pb4 = (const float4*)(z_prob + (size_t)b * HW);
        float4 a0 = zp4[lane*2], a1 = zp4[lane*2+1];
        float4 p0 = pb4[lane*2], p1 = pb4[lane*2+1];

        float smp[8] = { rintf(a0.x), rintf(a0.y), rintf(a0.z), rintf(a0.w),
                         rintf(a1.x), rintf(a1.y), rintf(a1.z), rintf(a1.w) };
        float prv[8] = { p0.x, p0.y, p0.z, p0.w, p1.x, p1.y, p1.z, p1.w };

        float tot = 0.f;
        #pragma unroll
        for (int k = 0; k < 8; k++) tot += smp[k];
        float incl = tot;
        #pragma unroll
        for (int off = 1; off < 32; off <<= 1) {
            float o = __shfl_up_sync(FULLM, incl, off);
            if (lane >= off) incl += o;
        }
        float run = incl - tot;   // exclusive prefix (csf BEFORE step lane*8)
        #pragma unroll
        for (int k = 0; k < 8; k++) {
            int i = lane*8 + k;
            float pr = prv[k];
            float c0 = pr * __logf(pr + EPSF)
                     + (1.0f - pr) * __logf(1.0f - pr + EPSF);
            s_sc[w][i] = make_float2(smp[k], run);
            s_pc[w][i] = make_float2(pr, c0);
            run += smp[k];
        }
    }
    __syncwarp();

    // ---- initial count distribution cd0[j] ~ (1-p) p^j, normalized, FTZ ----
    // 8-lane group holds j = sub + 8k, k=0..5 (0..47); entries >=42 flush to exact 0.
    float e2   = (float)exp(2.0);
    float pf   = 1.0f / (e2 + 1.0f);
    float onem = 1.0f - pf;
    double pw[9];
    pw[0] = (double)pf;
    #pragma unroll
    for (int k = 1; k < 9; k++) pw[k] = pw[k-1] * pw[k-1];

    float cd[EPL], fj[EPL];
    #pragma unroll
    for (int k = 0; k < EPL; k++) {
        int j = sub + 8*k;                      // 0..47
        double acc = 1.0;
        int jj = j;
        #pragma unroll
        for (int q = 0; q < 9; q++) { if (jj & 1) acc *= pw[q]; jj >>= 1; }
        float wv = (float)acc * onem;
        if (wv < MINNORM) wv = 0.0f;            // ftz flush
        cd[k] = wv;
        fj[k] = (float)j;
    }
    float wsum = ((cd[0]+cd[1]) + (cd[2]+cd[3])) + (cd[4]+cd[5]);
    wsum += __shfl_xor_sync(FULLM, wsum, 1);
    wsum += __shfl_xor_sync(FULLM, wsum, 2);
    wsum += __shfl_xor_sync(FULLM, wsum, 4);
    #pragma unroll
    for (int k = 0; k < EPL; k++) {
        float v = cd[k] / wsum;
        if (v < MINNORM) v = 0.0f;
        cd[k] = v;
    }

    // ---- serial scan: 4-step packs; pin vote once per pack (pin absorbing,
    //      and live execution at pinned state emits exact closed-form nums) ----
    #pragma unroll 1
    for (int i4 = 0; i4 < HW/4; i4++) {
        float alive = 0.f;
        #pragma unroll
        for (int u = 0; u < 4; u++) {
            const int i = i4*4 + u;
            float2 sc = s_sc[w][i];
            float sA = sc.x, cs = sc.y;
            float ivd = s_invd[w][i];
            float d   = (float)(HW - i);
            float s1  = 1.0f - sA;                  // mult = s2*pzg + s1
            float s2  = sA + sA - 1.0f;

            float num0 = 0.f, num1 = 0.f;
            #pragma unroll
            for (int k = 0; k < EPL; k++) {
                float t = fminf(fmaxf(fj[k] - cs, 0.0f), d);
                float pzg = fmul_ftz(t, ivd);                 // clip(j-csf,0,d)/d
                if (k & 1) num1 = ffma_ftz(cd[k], pzg, num1); // p_z uses OLD cd
                else       num0 = ffma_ftz(cd[k], pzg, num0);
                float m = ffma_ftz(s2, pzg, s1);
                cd[k] = fmul_ftz(m, cd[k]);                   // ftz tail flush like ref
                if (u == 3)                                   // amortized pin probe
                    alive = fmaxf(alive, fminf(cd[k], t));
            }
            float p0 = fadd_ftz(cd[0], cd[1]);
            float p1 = fadd_ftz(cd[2], cd[3]);
            float p2 = fadd_ftz(cd[4], cd[5]);
            float nrm = fadd_ftz(fadd_ftz(p0, p1), p2);
            float num = fadd_ftz(num0, num1);
            // 3-level butterfly within each 8-lane replica group
            num = fadd_ftz(num, __shfl_xor_sync(FULLM, num, 1));
            nrm = fadd_ftz(nrm, __shfl_xor_sync(FULLM, nrm, 1));
            num = fadd_ftz(num, __shfl_xor_sync(FULLM, num, 2));
            nrm = fadd_ftz(nrm, __shfl_xor_sync(FULLM, nrm, 2));
            num = fadd_ftz(num, __shfl_xor_sync(FULLM, num, 4));
            nrm = fadd_ftz(nrm, __shfl_xor_sync(FULLM, nrm, 4));

            if (lane == 0) s_num[w][i] = num;     // KL deferred to epilogue

            // renorm: approx reciprocal (clip semantics preserved); invn >= 1
            float invn = frcp_approx(fmaxf(nrm, 1e-6f));
            #pragma unroll
            for (int k = 0; k < EPL; k++) cd[k] = fmul_ftz(cd[k], invn);
        }
        // pinned: no surviving support above csf -> num==0 exactly forever
        if (!__any_sync(FULLM, alive > 0.0f)) break;
    }
    __syncwarp();

    // ---- epilogue: all KLs in parallel (8 steps per lane), branch-free.
    //      num==0 (pinned/unreached) reproduces the closed form exactly:
    //      log(0+eps)=log(eps), log(1-0+eps)=log(1.0f)=0.  ----
    float kl[8];
    #pragma unroll
    for (int k = 0; k < 8; k++) {
        int i = lane*8 + k;
        float2 pc = s_pc[w][i];
        float num = s_num[w][i];
        float lpz  = __logf(num + EPSF);
        float l1pz = __logf(1.0f - num + EPSF);
        kl[k] = pc.y - pc.x * lpz - (1.0f - pc.x) * l1pz;
    }

    // ---- coalesced float4 store of this warp's row ----
    float* ob = out + (size_t)b * HW;
    ((float4*)ob)[lane*2]   = make_float4(kl[0], kl[1], kl[2], kl[3]);
    ((float4*)ob)[lane*2+1] = make_float4(kl[4], kl[5], kl[6], kl[7]);
}

extern "C" void kernel_launch(void* const* d_in, const int* in_sizes, int n_in,
                              void* d_out, int out_size)
{
    const float* z_pres = (const float*)d_in[0];
    const float* z_prob = (const float*)d_in[1];
    float* out = (float*)d_out;
    int B = in_sizes[0] / HW;            // 1024
    spair_obj_kl_kernel<<<B / NWARP, NWARP*32>>>(z_pres, z_prob, out);
}